// round 16
// baseline (speedup 1.0000x reference)
#include <cuda_runtime.h>
#include <cuda_bf16.h>
#include <cstdint>

// ---------------- problem constants ----------------
#define SS    1024
#define INW   32
#define HH    128
#define NTHR  512          // 16 warps: (wp 0..7 = unit group) x (tp 0..1 = gate-type pair)
#define NBLK  128          // 4 batch rows per CTA
#define KTOT  160          // 128 h + 32 x
#define NKT   10           // k16 tiles
#define BST   168          // B staging stride in bf16 (conflict-free)
// staging: 8 rows; rows 0..3 = hi(batch 0..3), rows 4..7 = lo(batch 0..3)
#define BSTAGE_BYTES (8 * BST * 2)      // 2688, x2 ping-pong
#define EXSTR 5            // exchange stride per unit (floats)

#define OFF_ALO    0
#define ALO_BYTES  (512 * KTOT * 2)            // 163840: W_lo bf16 fragments (16w x 2mt x 10kt)
#define OFF_B      ALO_BYTES                    // 163840: 2 ping-pong staging buffers
#define OFF_EXG    (OFF_B + 2 * BSTAGE_BYTES)  // 169216: tanh(g) exchange [128][EXSTR]
#define OFF_EXO    (OFF_EXG + 128 * EXSTR * 4) // 171776: sigm(o) exchange
#define OFF_LRED   (OFF_EXO + 128 * EXSTR * 4) // 174336
#define SMEM_BYTES (OFF_LRED + 256)            // 174592

// ---------------- helpers ----------------
__device__ __forceinline__ unsigned short bf16_bits(float v) {
    __nv_bfloat16 b = __float2bfloat16(v);
    return *reinterpret_cast<unsigned short*>(&b);
}
__device__ __forceinline__ float bf16_val(unsigned short s) {
    __nv_bfloat16 b = *reinterpret_cast<__nv_bfloat16*>(&s);
    return __bfloat162float(b);
}
__device__ __forceinline__ void split_bf16(float w, unsigned short& hi, unsigned short& lo) {
    hi = bf16_bits(w);
    lo = bf16_bits(w - bf16_val(hi));
}
__device__ __forceinline__ uint32_t pack2(unsigned short a16, unsigned short b16) {
    return (uint32_t)a16 | ((uint32_t)b16 << 16);
}
__device__ __forceinline__ void mma_bf16(float& d0, float& d1, float& d2, float& d3,
                                         uint32_t a0, uint32_t a1, uint32_t a2, uint32_t a3,
                                         uint32_t b0, uint32_t b1) {
    asm volatile(
        "mma.sync.aligned.m16n8k16.row.col.f32.bf16.bf16.f32 "
        "{%0,%1,%2,%3}, {%4,%5,%6,%7}, {%8,%9}, {%0,%1,%2,%3};"
        : "+f"(d0), "+f"(d1), "+f"(d2), "+f"(d3)
        : "r"(a0), "r"(a1), "r"(a2), "r"(a3), "r"(b0), "r"(b1));
}
__device__ __forceinline__ float sigmoid_f(float v) {
    return __fdividef(1.0f, 1.0f + __expf(-v));
}
__device__ __forceinline__ float tanh_f(float v) {
    return 1.0f - __fdividef(2.0f, __expf(2.0f * v) + 1.0f);
}

__global__ void __launch_bounds__(NTHR, 1)
lstm_mma_kernel(const float* __restrict__ x,     // [B,S,IN]
                const float* __restrict__ Wih,   // [4H,IN]
                const float* __restrict__ Whh,   // [4H,H]
                const float* __restrict__ bih,   // [4H]
                const float* __restrict__ bhh,   // [4H]
                const float* __restrict__ Wlin,  // [1, S*H]
                const float* __restrict__ blin,  // [1]
                float* __restrict__ out)         // [B,1]
{
    extern __shared__ char smc[];
    float* smf = reinterpret_cast<float*>(smc);
    const int tid  = threadIdx.x;
    const int wid  = tid >> 5;
    const int lane = tid & 31;
    const int wp   = wid & 7;            // unit group: units wp*16 .. wp*16+15
    const int tp   = wid >> 3;           // 0: gate types {0,1}=i,f ; 1: {2,3}=g,o
    const int b0   = blockIdx.x * 4;

    // ---------------- prologue ----------------
    for (int i = tid; i < (2 * BSTAGE_BYTES) / 4; i += NTHR)
        reinterpret_cast<uint32_t*>(smc + OFF_B)[i] = 0;
    if (tid < 64) smf[(OFF_LRED >> 2) + tid] = 0.0f;

    // W fragments. Warp (wp,tp), m-tile mt: gate type gt = tp*2+mt of units wp*16..+15:
    //   g = gt*128 + wp*16 + r (+8 for rg&1).
    // hi -> registers (2 mt x 10 kt x 4 = 80 regs); lo -> smem ALO.
    uint32_t wa[2][NKT][4];
    {
        const int r  = lane >> 2;
        const int kc = (lane & 3) * 2;
        #pragma unroll
        for (int mt = 0; mt < 2; mt++) {
            #pragma unroll
            for (int kt = 0; kt < NKT; kt++) {
                uint32_t lo4[4];
                #pragma unroll
                for (int rg = 0; rg < 4; rg++) {
                    int g = (tp * 2 + mt) * 128 + wp * 16 + r + ((rg & 1) ? 8 : 0);
                    int k = kt * 16 + kc + ((rg & 2) ? 8 : 0);
                    float2 w2;
                    if (k < HH) w2 = *reinterpret_cast<const float2*>(Whh + (size_t)g * HH + k);
                    else        w2 = *reinterpret_cast<const float2*>(Wih + (size_t)g * INW + (k - HH));
                    unsigned short h0, l0, h1, l1;
                    split_bf16(w2.x, h0, l0);
                    split_bf16(w2.y, h1, l1);
                    wa[mt][kt][rg] = pack2(h0, h1);
                    lo4[rg]        = pack2(l0, l1);
                }
                *reinterpret_cast<uint4*>(smc + OFF_ALO +
                    (size_t)((((wid * 2 + mt) * NKT + kt) * 32 + lane) * 16))
                    = make_uint4(lo4[0], lo4[1], lo4[2], lo4[3]);
            }
        }
    }

    // ew role: unit u_sel (via hiD), batch rows n, n+1
    const int  u_sel = wp * 16 + (lane >> 2) + ((lane & 2) ? 8 : 0);
    const int  n     = 2 * (lane & 1);
    const bool hiD   = (lane & 2) == 0;  // use d0/d1 if true else d2/d3
    float bgt[2];                        // biases for this warp's 2 gate types
    #pragma unroll
    for (int mt = 0; mt < 2; mt++)
        bgt[mt] = bih[(tp * 2 + mt) * 128 + u_sel] + bhh[(tp * 2 + mt) * 128 + u_sel];
    float cA = 0.0f, cB = 0.0f;          // c-states (tp0 only)
    float linA = 0.0f, linB = 0.0f;

    __syncthreads();                     // staging zero complete
    if (tid < 64) {                      // x(t=0) into buf 0
        int row = tid >> 4, i0 = (tid & 15) * 2;
        float2 xv = *reinterpret_cast<const float2*>(
            x + ((size_t)(b0 + row) * SS + 0) * INW + i0);
        unsigned short h0, l0, h1, l1;
        split_bf16(xv.x, h0, l0);
        split_bf16(xv.y, h1, l1);
        *reinterpret_cast<uint32_t*>(smc + OFF_B + (size_t)(row * BST + HH + i0) * 2)
            = pack2(h0, h1);
        *reinterpret_cast<uint32_t*>(smc + OFF_B + (size_t)((row + 4) * BST + HH + i0) * 2)
            = pack2(l0, l1);
    }
    __syncthreads();

    const int bn = lane >> 2;            // B fragment column 0..7
    const int bk = (lane & 3) * 2;

    // ---------------- main recurrence ----------------
    #pragma unroll 1
    for (int t = 0; t < SS; t++) {
        float wl = 0.0f;
        if (tp == 0) wl = __ldg(Wlin + (size_t)t * HH + u_sel);
        float2 xv = make_float2(0.0f, 0.0f);
        if (tid < 64) {
            int row = tid >> 4, i0 = (tid & 15) * 2;
            int tn = (t + 1 < SS) ? (t + 1) : (SS - 1);
            xv = *reinterpret_cast<const float2*>(
                x + ((size_t)(b0 + row) * SS + tn) * INW + i0);
        }

        const char* bbase = smc + OFF_B + (size_t)(t & 1) * BSTAGE_BYTES;

        // === MMA phase: B = [B_hi | B_lo]; A-terms hi (regs) + lo (smem) ===
        float d0[2], d1[2], d2[2], d3[2];
        #pragma unroll
        for (int mt = 0; mt < 2; mt++) { d0[mt] = 0.f; d1[mt] = 0.f; d2[mt] = 0.f; d3[mt] = 0.f; }

        #pragma unroll
        for (int kt = 0; kt < NKT; kt++) {
            const char* bb = bbase + (size_t)((bn * BST + kt * 16 + bk) * 2);
            uint32_t bb0 = *reinterpret_cast<const uint32_t*>(bb);
            uint32_t bb1 = *reinterpret_cast<const uint32_t*>(bb + 16);
            #pragma unroll
            for (int mt = 0; mt < 2; mt++)
                mma_bf16(d0[mt], d1[mt], d2[mt], d3[mt],
                         wa[mt][kt][0], wa[mt][kt][1], wa[mt][kt][2], wa[mt][kt][3],
                         bb0, bb1);
            #pragma unroll
            for (int mt = 0; mt < 2; mt++) {
                const uint4 alo = *reinterpret_cast<const uint4*>(smc + OFF_ALO +
                    (size_t)((((wid * 2 + mt) * NKT + kt) * 32 + lane) * 16));
                mma_bf16(d0[mt], d1[mt], d2[mt], d3[mt],
                         alo.x, alo.y, alo.z, alo.w, bb0, bb1);
            }
        }

        // cross-column reduce (hi+lo): after this every lane holds valid preacts
        #pragma unroll
        for (int mt = 0; mt < 2; mt++) {
            d0[mt] += __shfl_xor_sync(0xffffffffu, d0[mt], 2);
            d1[mt] += __shfl_xor_sync(0xffffffffu, d1[mt], 2);
            d2[mt] += __shfl_xor_sync(0xffffffffu, d2[mt], 2);
            d3[mt] += __shfl_xor_sync(0xffffffffu, d3[mt], 2);
        }

        // preacts for this lane's 2 cells (u_sel, n) and (u_sel, n+1)
        float pA[2], pB[2];
        #pragma unroll
        for (int mt = 0; mt < 2; mt++) {
            pA[mt] = (hiD ? d0[mt] : d2[mt]) + bgt[mt];
            pB[mt] = (hiD ? d1[mt] : d3[mt]) + bgt[mt];
        }

        char* nbase = smc + OFF_B + (size_t)((t + 1) & 1) * BSTAGE_BYTES;

        if (tp == 1) {
            // produce tanh(g), sigmoid(o) and publish to paired warp
            float gvA = tanh_f(pA[0]);
            float ovA = sigmoid_f(pA[1]);
            float gvB = tanh_f(pB[0]);
            float ovB = sigmoid_f(pB[1]);
            smf[(OFF_EXG >> 2) + u_sel * EXSTR + n]     = gvA;
            smf[(OFF_EXG >> 2) + u_sel * EXSTR + n + 1] = gvB;
            smf[(OFF_EXO >> 2) + u_sel * EXSTR + n]     = ovA;
            smf[(OFF_EXO >> 2) + u_sel * EXSTR + n + 1] = ovB;
        }
        // pair barrier: tp1's exchange writes visible to tp0
        asm volatile("bar.sync %0, %1;" :: "r"(wp + 1), "r"(64) : "memory");

        if (tp == 0) {
            float ivA = sigmoid_f(pA[0]);
            float fvA = sigmoid_f(pA[1]);
            float ivB = sigmoid_f(pB[0]);
            float fvB = sigmoid_f(pB[1]);
            float gvA = smf[(OFF_EXG >> 2) + u_sel * EXSTR + n];
            float gvB = smf[(OFF_EXG >> 2) + u_sel * EXSTR + n + 1];
            float ovA = smf[(OFF_EXO >> 2) + u_sel * EXSTR + n];
            float ovB = smf[(OFF_EXO >> 2) + u_sel * EXSTR + n + 1];

            cA = fmaf(fvA, cA, ivA * gvA);
            cB = fmaf(fvB, cB, ivB * gvB);
            float hvA = ovA * tanh_f(cA);
            float hvB = ovB * tanh_f(cB);
            linA = fmaf(hvA, wl, linA);
            linB = fmaf(hvB, wl, linB);

            unsigned short hA, lA, hB, lB;
            split_bf16(hvA, hA, lA);
            split_bf16(hvB, hB, lB);
            *reinterpret_cast<unsigned short*>(nbase + (size_t)(n * BST + u_sel) * 2)       = hA;
            *reinterpret_cast<unsigned short*>(nbase + (size_t)((n + 4) * BST + u_sel) * 2) = lA;
            *reinterpret_cast<unsigned short*>(nbase + (size_t)((n + 1) * BST + u_sel) * 2) = hB;
            *reinterpret_cast<unsigned short*>(nbase + (size_t)((n + 5) * BST + u_sel) * 2) = lB;
        }
        // x(t+1) into next buffer
        if (tid < 64) {
            int row = tid >> 4, i0 = (tid & 15) * 2;
            unsigned short h0, l0, h1, l1;
            split_bf16(xv.x, h0, l0);
            split_bf16(xv.y, h1, l1);
            *reinterpret_cast<uint32_t*>(nbase + (size_t)(row * BST + HH + i0) * 2)
                = pack2(h0, h1);
            *reinterpret_cast<uint32_t*>(nbase + (size_t)((row + 4) * BST + HH + i0) * 2)
                = pack2(l0, l1);
        }
        __syncthreads();                 // staging complete for t+1
    }

    // ---------------- epilogue ----------------
    // tp0 lanes: linA = partial for row n, linB for n+1 (n = 2*(lane&1)).
    #pragma unroll
    for (int off = 2; off <= 16; off <<= 1) {
        linA += __shfl_xor_sync(0xffffffffu, linA, off);
        linB += __shfl_xor_sync(0xffffffffu, linB, off);
    }
    if (tp == 0 && lane < 2) {
        smf[(OFF_LRED >> 2) + wp * 4 + 2 * lane]     = linA;   // row 2*lane
        smf[(OFF_LRED >> 2) + wp * 4 + 2 * lane + 1] = linB;   // row 2*lane+1
    }
    __syncthreads();
    if (tid < 4) {
        float s = blin[0];
        #pragma unroll
        for (int w = 0; w < 8; w++) s += smf[(OFF_LRED >> 2) + w * 4 + tid];
        out[b0 + tid] = s;
    }
}

extern "C" void kernel_launch(void* const* d_in, const int* in_sizes, int n_in,
                              void* d_out, int out_size)
{
    const float* x    = (const float*)d_in[0];
    const float* Wih  = (const float*)d_in[1];
    const float* Whh  = (const float*)d_in[2];
    const float* bih  = (const float*)d_in[3];
    const float* bhh  = (const float*)d_in[4];
    const float* Wlin = (const float*)d_in[5];
    const float* blin = (const float*)d_in[6];
    float* out = (float*)d_out;

    cudaFuncSetAttribute(lstm_mma_kernel,
                         cudaFuncAttributeMaxDynamicSharedMemorySize, SMEM_BYTES);
    lstm_mma_kernel<<<NBLK, NTHR, SMEM_BYTES>>>(x, Wih, Whh, bih, bhh, Wlin, blin, out);
}